// round 10
// baseline (speedup 1.0000x reference)
#include <cuda_runtime.h>
#include <cstdint>

#define BST 136
#define BBUF (32*BST)                      // floats per B buffer
#define AF_BYTES 32768
#define BS_BYTES (2*BBUF*4)                // 34816
#define FA_BYTES 16384
#define SMEM_BYTES (AF_BYTES + BS_BYTES + FA_BYTES)

__device__ float g_fcT[26214400];          // tf32-rounded coeffs, fc layout

__device__ __forceinline__ uint32_t f2tf(float f){
    uint32_t u; asm("cvt.rna.tf32.f32 %0, %1;" : "=r"(u) : "f"(f)); return u;
}
__device__ __forceinline__ void mma8(float* d, const uint4 a, uint32_t b0, uint32_t b1){
    asm volatile("mma.sync.aligned.m16n8k8.row.col.f32.tf32.tf32.f32 "
        "{%0,%1,%2,%3}, {%4,%5,%6,%7}, {%8,%9}, {%0,%1,%2,%3};"
        : "+f"(d[0]),"+f"(d[1]),"+f"(d[2]),"+f"(d[3])
        : "r"(a.x),"r"(a.y),"r"(a.z),"r"(a.w), "r"(b0),"r"(b1));
}
__device__ __forceinline__ void cpa16(uint32_t s, const float* g){
    asm volatile("cp.async.cg.shared.global [%0], [%1], 16;" :: "r"(s), "l"(g));
}
__device__ __forceinline__ unsigned long long pk2(float v){
    unsigned long long r; asm("mov.b64 %0, {%1, %1};" : "=l"(r) : "f"(v)); return r;
}
__device__ __forceinline__ float2 upk(unsigned long long v){
    float2 r; asm("mov.b64 {%0, %1}, %2;" : "=f"(r.x), "=f"(r.y) : "l"(v)); return r;
}
__device__ __forceinline__ void fma2(unsigned long long& d, unsigned long long a, unsigned long long b){
    asm("fma.rn.f32x2 %0, %1, %2, %0;" : "+l"(d) : "l"(a), "l"(b));
}

__global__ void init_out_kernel(const float* __restrict__ bias, float* __restrict__ out){
    int i = blockIdx.x*256 + threadIdx.x;
    out[i] = bias[i & 511];
}
__global__ void prep_kernel(const float* __restrict__ fc){
    size_t i = ((size_t)blockIdx.x*256 + threadIdx.x)*4;
    float4 v = *(const float4*)(fc + i);
    *(uint4*)(g_fcT + i) = make_uint4(f2tf(v.x), f2tf(v.y), f2tf(v.z), f2tf(v.w));
}

struct Gen { float ss[8], cc[8], s1[8], c1[8]; };

__device__ __forceinline__ void init_state(Gen& G, const float* __restrict__ x,
                                            int m0, int MT_A, int gq, int ib, int ii0, float k0f){
#pragma unroll
    for (int mq=0; mq<2; ++mq){
        int m = m0 + 16*(MT_A+4*mq) + gq;
#pragma unroll
        for (int mh=0; mh<2; ++mh)
#pragma unroll
        for (int iv=0; iv<2; ++iv){
            int j = mq*4 + mh*2 + iv;
            float xv = x[(size_t)(m + 8*mh)*512 + ib + ii0 + 4*iv];
            sincospif(xv, &G.s1[j], &G.c1[j]);
            sincospif(k0f*xv, &G.ss[j], &G.cc[j]);
        }
    }
}
__device__ __forceinline__ void advance8(float* ss, float* cc, const float* s1, const float* c1){
#pragma unroll
    for (int j=0;j<8;++j){
        float ns = fmaf(ss[j], c1[j],  cc[j]*s1[j]);
        float nc = fmaf(cc[j], c1[j], -ss[j]*s1[j]);
        ss[j]=ns; cc[j]=nc;
    }
}
__device__ __forceinline__ void write_af(uint4* Af, int buf, int MT_A, int kts, int lw, const Gen& G){
    const int xl = lw ^ (4*(kts&1));
#pragma unroll
    for (int mq=0; mq<2; ++mq){
        int base = mq*4;
        int idx = buf*1024 + (MT_A + 4*mq)*128 + xl;
        Af[idx + kts*32]     = make_uint4(f2tf(G.ss[base+0]), f2tf(G.ss[base+2]),
                                          f2tf(G.ss[base+1]), f2tf(G.ss[base+3]));
        Af[idx + (kts+2)*32] = make_uint4(f2tf(G.cc[base+0]), f2tf(G.cc[base+2]),
                                          f2tf(G.cc[base+1]), f2tf(G.cc[base+3]));
    }
}

__global__ void __launch_bounds__(384,1)
fkan_hybrid(const float* __restrict__ x, float* __restrict__ out)
{
    extern __shared__ char smem[];
    uint4* Af = (uint4*)smem;
    float* Bs = (float*)(smem + AF_BYTES);
    float* FA = (float*)(smem + AF_BYTES + BS_BYTES);
    const uint32_t bs_sa = (uint32_t)__cvta_generic_to_shared(Bs);

    const int tid  = threadIdx.x;
    const int lane = tid & 31;
    const int wid  = tid >> 5;

    const int m0 = blockIdx.x*128, n0 = blockIdx.y*128, g0 = blockIdx.z*5;
    const float k0f = (float)(g0 + 1);
    const bool isH = (tid < 256);

    // ---- HMMA indexing ----
    const int gid = lane >> 2, tig = lane & 3;
    const int wm = wid >> 2, wn = wid & 3;
    const int MT_A = tid>>6;
    const int gq = (tid>>3)&7, iq = tid&7;
    const int ii0 = ((iq>>2)<<3)|(iq&3);
    const int lw  = 4*gq + (iq&3);
    const int kts = ii0>>3;

    // ---- FFMA indexing (tid 256..383) ----
    const int ft   = tid - 256;                 // 0..127
    const int fkk  = ft >> 3;                   // state kk 0..15
    const int fmo  = (ft & 7) << 3;             // state m-octet
    const int ftm  = ft >> 4;                   // out m-octet 0..7
    const int ftn  = ft & 15;                   // out n-octet 0..15
    const int fm0  = 1408 + blockIdx.x*64;
    const bool fact = (blockIdx.x < 10);

    // ---- B cp.async mapping (HMMA threads only) ----
    const float* bsrc[4]; uint32_t bdst[4];
#pragma unroll
    for (int q=0;q<4;++q){
        int c4 = q*256 + (tid & 255), row = c4>>5, col4 = c4&31;
        int f = row>>4, ii = row&15;
        bsrc[q] = g_fcT + (size_t)f*13107200 + (size_t)g0*262144 + (size_t)ii*512 + n0 + 4*col4;
        bdst[q] = bs_sa + (uint32_t)(row*BST + 4*col4)*4;
    }

    float acc[4][4][4];
    unsigned long long fac[8][4];
    if (isH){
#pragma unroll
        for (int a=0;a<4;++a)
#pragma unroll
        for (int b=0;b<4;++b)
#pragma unroll
        for (int c=0;c<4;++c) acc[a][b][c]=0.f;
    } else {
#pragma unroll
        for (int a=0;a<8;++a)
#pragma unroll
        for (int b=0;b<4;++b) fac[a][b]=0ull;
    }

    Gen G;                                  // HMMA states
    float fss[8], fcc[8], fs1[8], fc1[8];   // FFMA states

    // ---- prologue ----
    if (isH){
        init_state(G, x, m0, MT_A, gq, 0, ii0, k0f);
        write_af(Af, 0, MT_A, kts, lw, G);
#pragma unroll
        for (int q=0;q<4;++q) cpa16(bdst[q], bsrc[q]);
    } else {
#pragma unroll
        for (int j=0;j<8;++j){
            if (fact){
                float xv = x[(size_t)(fm0 + fmo + j)*512 + fkk];
                sincospif(xv, &fs1[j], &fc1[j]);
                sincospif(k0f*xv, &fss[j], &fcc[j]);
            } else { fs1[j]=fc1[j]=fss[j]=fcc[j]=0.f; }
        }
#pragma unroll
        for (int j=0;j<2;++j){
            *(float4*)&FA[fkk*128 + 0*64 + fmo + 4*j] = *(float4*)&fss[4*j];
            *(float4*)&FA[fkk*128 + 1*64 + fmo + 4*j] = *(float4*)&fcc[4*j];
        }
    }
    asm volatile("cp.async.commit_group;");

    int t = 0;
    for (int c=0; c<32; ++c){
        for (int gI=0; gI<5; ++gI, ++t){
            const int cur = t&1, nxt = cur^1;
            const bool hn = (t < 159);
            // advance / re-init states (before sync, overlapped)
            if (hn){
                if (isH){
                    if (gI < 4) advance8(G.ss, G.cc, G.s1, G.c1);
                    else init_state(G, x, m0, MT_A, gq, (c+1)*16, ii0, k0f);
                } else {
                    if (gI < 4) advance8(fss, fcc, fs1, fc1);
                    else {
#pragma unroll
                        for (int j=0;j<8;++j){
                            if (fact){
                                float xv = x[(size_t)(fm0 + fmo + j)*512 + (c+1)*16 + fkk];
                                sincospif(xv, &fs1[j], &fc1[j]);
                                sincospif(k0f*xv, &fss[j], &fcc[j]);
                            }
                        }
                    }
                }
            }
            asm volatile("cp.async.wait_group 0;");
            __syncthreads();
            if (hn){
                if (isH){
                    int gN = (gI<4)? gI+1 : 0;
                    int cN = (gI<4)? c : c+1;
                    size_t go = (size_t)gN*262144 + (size_t)cN*8192;
#pragma unroll
                    for (int q=0;q<4;++q) cpa16(bdst[q] + nxt*(BBUF*4), bsrc[q]+go);
                    write_af(Af, nxt, MT_A, kts, lw, G);
                } else {
#pragma unroll
                    for (int j=0;j<2;++j){
                        *(float4*)&FA[nxt*2048 + fkk*128 + 0*64 + fmo + 4*j] = *(float4*)&fss[4*j];
                        *(float4*)&FA[nxt*2048 + fkk*128 + 1*64 + fmo + 4*j] = *(float4*)&fcc[4*j];
                    }
                }
            }
            asm volatile("cp.async.commit_group;");

            if (isH){
                // ---- HMMA: 64 mma over 32-wide K ----
                const uint4* Aw = Af + cur*1024 + wm*512;
                const float* Bw = Bs + cur*BBUF + wn*32;
#pragma unroll
                for (int kt=0; kt<4; ++kt){
                    const int xo = 4*(kt&1);
                    uint4 a[4];
#pragma unroll
                    for (int mt=0;mt<4;++mt) a[mt] = Aw[mt*128 + kt*32 + (lane ^ xo)];
#pragma unroll
                    for (int nt=0;nt<4;++nt){
                        uint32_t b0 = __float_as_uint(Bw[(kt*8+tig)*BST   + nt*8 + gid]);
                        uint32_t b1 = __float_as_uint(Bw[(kt*8+tig+4)*BST + nt*8 + gid]);
#pragma unroll
                        for (int mt=0;mt<4;++mt) mma8(acc[mt][nt], a[mt], b0, b1);
                    }
                }
            } else {
                // ---- FFMA2: 64m x 128n, K=32 ----
                const float* fa = FA + cur*2048;
                const float* bw = Bs + cur*BBUF;
#pragma unroll 4
                for (int kk=0; kk<16; ++kk){
                    float4 as0 = *(const float4*)&fa[kk*128 + ftm*8];
                    float4 as1 = *(const float4*)&fa[kk*128 + ftm*8 + 4];
                    float4 ac0 = *(const float4*)&fa[kk*128 + 64 + ftm*8];
                    float4 ac1 = *(const float4*)&fa[kk*128 + 64 + ftm*8 + 4];
                    ulonglong2 bs0 = *(const ulonglong2*)&bw[kk*BST + ftn*8];
                    ulonglong2 bs1 = *(const ulonglong2*)&bw[kk*BST + ftn*8 + 4];
                    ulonglong2 bc0 = *(const ulonglong2*)&bw[(16+kk)*BST + ftn*8];
                    ulonglong2 bc1 = *(const ulonglong2*)&bw[(16+kk)*BST + ftn*8 + 4];
                    float as[8] = {as0.x,as0.y,as0.z,as0.w,as1.x,as1.y,as1.z,as1.w};
                    float ac[8] = {ac0.x,ac0.y,ac0.z,ac0.w,ac1.x,ac1.y,ac1.z,ac1.w};
#pragma unroll
                    for (int r=0;r<8;++r){
                        unsigned long long ad = pk2(as[r]);
                        fma2(fac[r][0], ad, bs0.x); fma2(fac[r][1], ad, bs0.y);
                        fma2(fac[r][2], ad, bs1.x); fma2(fac[r][3], ad, bs1.y);
                    }
#pragma unroll
                    for (int r=0;r<8;++r){
                        unsigned long long ad = pk2(ac[r]);
                        fma2(fac[r][0], ad, bc0.x); fma2(fac[r][1], ad, bc0.y);
                        fma2(fac[r][2], ad, bc1.x); fma2(fac[r][3], ad, bc1.y);
                    }
                }
            }
        }
    }

    // ---- epilogues ----
    if (isH){
#pragma unroll
        for (int mt=0;mt<4;++mt)
#pragma unroll
        for (int nt=0;nt<4;++nt){
            float* op = out + (size_t)(m0 + wm*64 + mt*16 + gid)*512 + n0 + wn*32 + nt*8 + 2*tig;
            atomicAdd(op,      acc[mt][nt][0]);
            atomicAdd(op+1,    acc[mt][nt][1]);
            atomicAdd(op+4096, acc[mt][nt][2]);
            atomicAdd(op+4097, acc[mt][nt][3]);
        }
    } else if (fact){
#pragma unroll
        for (int r=0;r<8;++r)
#pragma unroll
        for (int p=0;p<4;++p){
            float2 v = upk(fac[r][p]);
            float* op = out + (size_t)(fm0 + ftm*8 + r)*512 + n0 + ftn*8 + 2*p;
            atomicAdd(op,   v.x);
            atomicAdd(op+1, v.y);
        }
    }
}

extern "C" void kernel_launch(void* const* d_in, const int* in_sizes, int n_in,
                              void* d_out, int out_size) {
    const float* x    = (const float*)d_in[0];
    const float* fc   = (const float*)d_in[1];
    const float* bias = (const float*)d_in[2];
    float* out = (float*)d_out;

    cudaFuncSetAttribute(fkan_hybrid, cudaFuncAttributeMaxDynamicSharedMemorySize, SMEM_BYTES);

    init_out_kernel<<<4096, 256>>>(bias, out);
    prep_kernel<<<25600, 256>>>(fc);
    fkan_hybrid<<<dim3(11,4,10), 384, SMEM_BYTES>>>(x, out);
}

// round 11
// speedup vs baseline: 4.0460x; 4.0460x over previous
#include <cuda_runtime.h>
#include <cuda_fp16.h>
#include <cstdint>

#define NUNITS 2048
#define NCTAS  148
#define GST    262144              // halfs per (f,g) slab

__device__ __half g_fcH[26214400];  // [f][g][o][i], scaled by 256

__device__ __forceinline__ void cpa16(uint32_t s, const void* g){
    asm volatile("cp.async.cg.shared.global [%0], [%1], 16;" :: "r"(s), "l"(g));
}
__device__ __forceinline__ uint32_t ph2(float lo, float hi){
    __half2 h = __floats2half2_rn(lo, hi);
    return *reinterpret_cast<uint32_t*>(&h);
}
__device__ __forceinline__ void mma16(float* d, const uint4 a, uint32_t b0, uint32_t b1){
    asm volatile("mma.sync.aligned.m16n8k16.row.col.f32.f16.f16.f32 "
        "{%0,%1,%2,%3}, {%4,%5,%6,%7}, {%8,%9}, {%0,%1,%2,%3};"
        : "+f"(d[0]),"+f"(d[1]),"+f"(d[2]),"+f"(d[3])
        : "r"(a.x),"r"(a.y),"r"(a.z),"r"(a.w), "r"(b0),"r"(b1));
}

__global__ void init_out_kernel(const float* __restrict__ bias, float* __restrict__ out){
    int i = blockIdx.x*256 + threadIdx.x;
    out[i] = bias[i & 511];
}

// transpose fc[q][i][o] -> g_fcH[q][o][i] * 256, fp16
__global__ void __launch_bounds__(256) prep_kernel(const float* __restrict__ fc){
    __shared__ float t[32][33];
    int q = blockIdx.z, i0 = blockIdx.x*32, o0 = blockIdx.y*32;
    const float* src = fc + (size_t)q*GST;
    __half* dst = g_fcH + (size_t)q*GST;
    int tx = threadIdx.x, ty = threadIdx.y;
#pragma unroll
    for (int j=0;j<4;++j) t[ty+8*j][tx] = src[(size_t)(i0+ty+8*j)*512 + o0+tx];
    __syncthreads();
    int tid = ty*32+tx, o = tid>>3, s = tid&7;
    float v0 = t[s*4+0][o]*256.f, v1 = t[s*4+1][o]*256.f;
    float v2 = t[s*4+2][o]*256.f, v3 = t[s*4+3][o]*256.f;
    uint2 w = make_uint2(ph2(v0,v1), ph2(v2,v3));
    *(uint2*)(dst + (size_t)(o0+o)*512 + i0 + s*4) = w;
}

__global__ void __launch_bounds__(256,1)
fkan_fp16(const float* __restrict__ x, float* __restrict__ out)
{
    __shared__ __align__(16) uint4  Af[2][16][32];     // [buf][mtile*2+kt][lane]
    __shared__ __align__(16) __half Bs[2][128][40];    // [buf][n][k], 8-half row pad

    const int tid  = threadIdx.x;
    const int lane = tid & 31;
    const int wid  = tid >> 5;
    const int gid  = lane >> 2, tig = lane & 3;
    const int wm   = wid >> 2,  wn  = wid & 3;
    // generator indexing: thread owns (mtile, b, a): m in {b, b+8}, i in {2a,2a+1,2a+8,2a+9}
    const int mtile = wid;              // warp == mtile (coalesced Af writes)
    const int gb = lane >> 2, ga = lane & 3;

    // cp.async chunk mapping (2 chunks per thread)
    int cf[2], co[2], cio[2]; uint32_t cdst[2];
    const uint32_t bs_sa = (uint32_t)__cvta_generic_to_shared(&Bs[0][0][0]);
#pragma unroll
    for (int q=0;q<2;++q){
        int cidx = q*256 + tid;
        cio[q] = cidx & 1; co[q] = (cidx>>1) & 127; cf[q] = cidx>>8;
        cdst[q] = bs_sa + (uint32_t)(co[q]*80 + cf[q]*32 + cio[q]*16);
    }

    const int c = blockIdx.x;
    const int u0 = (NUNITS*c)/NCTAS, u1 = (NUNITS*(c+1))/NCTAS;

    float acc[4][4][4];
#pragma unroll
    for (int a1=0;a1<4;++a1)
#pragma unroll
    for (int b1=0;b1<4;++b1)
#pragma unroll
    for (int d1=0;d1<4;++d1) acc[a1][b1][d1]=0.f;

    int cur_tile = -1, cm0 = 0, cn0 = 0;
    const float SC = 1.f/256.f;

    for (int u = u0; u < u1; ++u){
        const int tile = u >> 5, ic = u & 31;
        const int m0 = (tile>>2)*128, n0 = (tile&3)*128, ib = ic*16;

        if (tile != cur_tile){
            if (cur_tile >= 0){
#pragma unroll
                for (int mt=0;mt<4;++mt)
#pragma unroll
                for (int nt=0;nt<4;++nt){
                    float* op = out + (size_t)(cm0 + wm*64 + mt*16 + gid)*512 + cn0 + wn*32 + nt*8 + 2*tig;
                    atomicAdd(op,      acc[mt][nt][0]*SC);
                    atomicAdd(op+1,    acc[mt][nt][1]*SC);
                    atomicAdd(op+4096, acc[mt][nt][2]*SC);
                    atomicAdd(op+4097, acc[mt][nt][3]*SC);
                }
#pragma unroll
                for (int a1=0;a1<4;++a1)
#pragma unroll
                for (int b1=0;b1<4;++b1)
#pragma unroll
                for (int d1=0;d1<4;++d1) acc[a1][b1][d1]=0.f;
            }
            cur_tile = tile; cm0 = m0; cn0 = n0;
        }

        // ---- init rotation states (k=1) ----
        float ss[8], cc[8], s1[8], c1[8];
#pragma unroll
        for (int mh=0; mh<2; ++mh)
#pragma unroll
        for (int iv=0; iv<4; ++iv){
            int j = mh*4 + iv;
            int i = ib + (iv&1) + 2*ga + 8*(iv>>1);
            int m = m0 + mtile*16 + gb + 8*mh;
            float xv = __ldg(x + (size_t)m*512 + i);
            sincospif(xv, &s1[j], &c1[j]);
            ss[j]=s1[j]; cc[j]=c1[j];
        }

        // B gmem base pointers for this unit (per chunk)
        const __half* gb0 = g_fcH + ((size_t)(cf[0]*50)*512 + n0 + co[0])*512 + ib + cio[0]*8;
        const __half* gb1 = g_fcH + ((size_t)(cf[1]*50)*512 + n0 + co[1])*512 + ib + cio[1]*8;

        // ---- prologue: Af[0] + B(g=0) ----
        Af[0][mtile*2+0][lane] = make_uint4(ph2(ss[0],ss[1]), ph2(ss[4],ss[5]),
                                            ph2(ss[2],ss[3]), ph2(ss[6],ss[7]));
        Af[0][mtile*2+1][lane] = make_uint4(ph2(cc[0],cc[1]), ph2(cc[4],cc[5]),
                                            ph2(cc[2],cc[3]), ph2(cc[6],cc[7]));
        cpa16(cdst[0], gb0);
        cpa16(cdst[1], gb1);
        asm volatile("cp.async.commit_group;");

        for (int g=0; g<50; ++g){
            const int cur = g&1, nxt = cur^1;
            const bool hn = (g < 49);
            if (hn){
#pragma unroll
                for (int j=0;j<8;++j){
                    float ns = fmaf(ss[j], c1[j],  cc[j]*s1[j]);
                    float nc = fmaf(cc[j], c1[j], -ss[j]*s1[j]);
                    ss[j]=ns; cc[j]=nc;
                }
            }
            asm volatile("cp.async.wait_group 0;");
            __syncthreads();
            if (hn){
                Af[nxt][mtile*2+0][lane] = make_uint4(ph2(ss[0],ss[1]), ph2(ss[4],ss[5]),
                                                      ph2(ss[2],ss[3]), ph2(ss[6],ss[7]));
                Af[nxt][mtile*2+1][lane] = make_uint4(ph2(cc[0],cc[1]), ph2(cc[4],cc[5]),
                                                      ph2(cc[2],cc[3]), ph2(cc[6],cc[7]));
                size_t go = (size_t)(g+1)*GST;
                cpa16(cdst[0] + nxt*10240u, gb0 + go);
                cpa16(cdst[1] + nxt*10240u, gb1 + go);
                asm volatile("cp.async.commit_group;");
            }
            // ---- GEMM: 128m x 128n x 32k (fp16 HMMA) ----
#pragma unroll
            for (int kt=0; kt<2; ++kt){
                uint4 av[4];
#pragma unroll
                for (int mt=0;mt<4;++mt) av[mt] = Af[cur][(wm*4+mt)*2 + kt][lane];
#pragma unroll
                for (int nt=0;nt<4;++nt){
                    const __half* bp = &Bs[cur][wn*32 + nt*8 + gid][kt*16 + 2*tig];
                    uint32_t b0 = *(const uint32_t*)bp;
                    uint32_t b1 = *(const uint32_t*)(bp + 8);
#pragma unroll
                    for (int mt=0;mt<4;++mt) mma16(acc[mt][nt], av[mt], b0, b1);
                }
            }
            __syncthreads();
        }
    }

    // final flush
    if (cur_tile >= 0){
#pragma unroll
        for (int mt=0;mt<4;++mt)
#pragma unroll
        for (int nt=0;nt<4;++nt){
            float* op = out + (size_t)(cm0 + wm*64 + mt*16 + gid)*512 + cn0 + wn*32 + nt*8 + 2*tig;
            atomicAdd(op,      acc[mt][nt][0]*SC);
            atomicAdd(op+1,    acc[mt][nt][1]*SC);
            atomicAdd(op+4096, acc[mt][nt][2]*SC);
            atomicAdd(op+4097, acc[mt][nt][3]*SC);
        }
    }
}

extern "C" void kernel_launch(void* const* d_in, const int* in_sizes, int n_in,
                              void* d_out, int out_size) {
    const float* x    = (const float*)d_in[0];
    const float* fc   = (const float*)d_in[1];
    const float* bias = (const float*)d_in[2];
    float* out = (float*)d_out;

    init_out_kernel<<<4096, 256>>>(bias, out);
    prep_kernel<<<dim3(16,16,100), dim3(32,8)>>>(fc);
    fkan_fp16<<<NCTAS, 256>>>(x, out);
}

// round 12
// speedup vs baseline: 4.9660x; 1.2274x over previous
#include <cuda_runtime.h>
#include <cuda_fp16.h>
#include <cstdint>

#define NUNITS 4096
#define NCTAS  296
#define GST    262144              // halfs per (f,g) slab

__device__ __half g_fcH[26214400];  // [f][g][o][i], scaled by 256

__device__ __forceinline__ void cpa16(uint32_t s, const void* g){
    asm volatile("cp.async.cg.shared.global [%0], [%1], 16;" :: "r"(s), "l"(g));
}
__device__ __forceinline__ uint32_t ph2(float lo, float hi){
    __half2 h = __floats2half2_rn(lo, hi);
    return *reinterpret_cast<uint32_t*>(&h);
}
__device__ __forceinline__ void mma16(float* d, const uint4 a, uint32_t b0, uint32_t b1){
    asm volatile("mma.sync.aligned.m16n8k16.row.col.f32.f16.f16.f32 "
        "{%0,%1,%2,%3}, {%4,%5,%6,%7}, {%8,%9}, {%0,%1,%2,%3};"
        : "+f"(d[0]),"+f"(d[1]),"+f"(d[2]),"+f"(d[3])
        : "r"(a.x),"r"(a.y),"r"(a.z),"r"(a.w), "r"(b0),"r"(b1));
}

__global__ void init_out_kernel(const float* __restrict__ bias, float* __restrict__ out){
    int i = (blockIdx.x*256 + threadIdx.x)*4;
    *(float4*)(out + i) = *(const float4*)(bias + (i & 511));
}

// transpose fc[q][i][o] -> g_fcH[q][o][i] * 256, fp16
__global__ void __launch_bounds__(256) prep_kernel(const float* __restrict__ fc){
    __shared__ float t[32][33];
    int q = blockIdx.z, i0 = blockIdx.x*32, o0 = blockIdx.y*32;
    const float* src = fc + (size_t)q*GST;
    __half* dst = g_fcH + (size_t)q*GST;
    int tx = threadIdx.x, ty = threadIdx.y;
#pragma unroll
    for (int j=0;j<4;++j) t[ty+8*j][tx] = src[(size_t)(i0+ty+8*j)*512 + o0+tx];
    __syncthreads();
    int tid = ty*32+tx, o = tid>>3, s = tid&7;
    float v0 = t[s*4+0][o]*256.f, v1 = t[s*4+1][o]*256.f;
    float v2 = t[s*4+2][o]*256.f, v3 = t[s*4+3][o]*256.f;
    uint2 w = make_uint2(ph2(v0,v1), ph2(v2,v3));
    *(uint2*)(dst + (size_t)(o0+o)*512 + i0 + s*4) = w;
}

__global__ void __launch_bounds__(128,2)
fkan_fp16(const float* __restrict__ x, float* __restrict__ out)
{
    __shared__ __align__(16) uint4  Af[2][16][32];     // [buf][mtile*2+kt][lane]
    __shared__ __align__(16) __half Bs[2][64][40];     // [buf][n][k], 8-half row pad

    const int tid  = threadIdx.x;
    const int lane = tid & 31;
    const int wid  = tid >> 5;           // 0..3
    const int gid  = lane >> 2, tig = lane & 3;
    const int wm   = wid >> 1,  wn  = wid & 1;
    const int gb   = lane >> 2, ga = lane & 3;

    // cp.async chunk mapping: 256 chunks of 16B per buffer, 2 per thread
    int cf[2], cco[2], ccio[2]; uint32_t cdst[2];
    const uint32_t bs_sa = (uint32_t)__cvta_generic_to_shared(&Bs[0][0][0]);
#pragma unroll
    for (int q=0;q<2;++q){
        int cidx = q*128 + tid;
        cf[q] = cidx>>7; cco[q] = (cidx>>1)&63; ccio[q] = cidx&1;
        cdst[q] = bs_sa + (uint32_t)(cco[q]*80 + cf[q]*32 + ccio[q]*16);
    }

    const int c = blockIdx.x;
    const int u0 = (NUNITS*c)/NCTAS, u1 = (NUNITS*(c+1))/NCTAS;

    float acc[4][4][4];
#pragma unroll
    for (int a1=0;a1<4;++a1)
#pragma unroll
    for (int b1=0;b1<4;++b1)
#pragma unroll
    for (int d1=0;d1<4;++d1) acc[a1][b1][d1]=0.f;

    int cur_tile = -1, cm0 = 0, cn0 = 0;
    const float SC = 1.f/256.f;

    for (int u = u0; u < u1; ++u){
        const int tile = u >> 5, ic = u & 31;
        const int m0 = (tile>>3)*128, n0 = (tile&7)*64, ib = ic*16;

        if (tile != cur_tile){
            if (cur_tile >= 0){
#pragma unroll
                for (int mt=0;mt<4;++mt)
#pragma unroll
                for (int nt=0;nt<4;++nt){
                    float* op = out + (size_t)(cm0 + wm*64 + mt*16 + gid)*512 + cn0 + wn*32 + nt*8 + 2*tig;
                    atomicAdd(op,      acc[mt][nt][0]*SC);
                    atomicAdd(op+1,    acc[mt][nt][1]*SC);
                    atomicAdd(op+4096, acc[mt][nt][2]*SC);
                    atomicAdd(op+4097, acc[mt][nt][3]*SC);
                }
#pragma unroll
                for (int a1=0;a1<4;++a1)
#pragma unroll
                for (int b1=0;b1<4;++b1)
#pragma unroll
                for (int d1=0;d1<4;++d1) acc[a1][b1][d1]=0.f;
            }
            cur_tile = tile; cm0 = m0; cn0 = n0;
        }

        // ---- init rotation states (k=1): 16 states/thread over 2 mtiles ----
        float ss[16], cc[16], s1[16], c1[16];
#pragma unroll
        for (int mq=0; mq<2; ++mq)
#pragma unroll
        for (int mh=0; mh<2; ++mh)
#pragma unroll
        for (int iv=0; iv<4; ++iv){
            int j = mq*8 + mh*4 + iv;
            int i = ib + 2*ga + (iv&1) + 8*(iv>>1);
            int m = m0 + (wid*2+mq)*16 + gb + 8*mh;
            float xv = __ldg(x + (size_t)m*512 + i);
            sincospif(xv, &s1[j], &c1[j]);
            ss[j]=s1[j]; cc[j]=c1[j];
        }

        const __half* gb0 = g_fcH + ((size_t)(cf[0]*50)*512 + n0 + cco[0])*512 + ib + ccio[0]*8;
        const __half* gb1 = g_fcH + ((size_t)(cf[1]*50)*512 + n0 + cco[1])*512 + ib + ccio[1]*8;

        // ---- prologue: Af[0] + B(g=0) ----
#pragma unroll
        for (int mq=0; mq<2; ++mq){
            int mtile = wid*2+mq, b = mq*8;
            Af[0][mtile*2+0][lane] = make_uint4(ph2(ss[b+0],ss[b+1]), ph2(ss[b+4],ss[b+5]),
                                                ph2(ss[b+2],ss[b+3]), ph2(ss[b+6],ss[b+7]));
            Af[0][mtile*2+1][lane] = make_uint4(ph2(cc[b+0],cc[b+1]), ph2(cc[b+4],cc[b+5]),
                                                ph2(cc[b+2],cc[b+3]), ph2(cc[b+6],cc[b+7]));
        }
        cpa16(cdst[0], gb0);
        cpa16(cdst[1], gb1);
        asm volatile("cp.async.commit_group;");

        for (int g=0; g<50; ++g){
            const int cur = g&1, nxt = cur^1;
            const bool hn = (g < 49);
            if (hn){
#pragma unroll
                for (int j=0;j<16;++j){
                    float ns = fmaf(ss[j], c1[j],  cc[j]*s1[j]);
                    float nc = fmaf(cc[j], c1[j], -ss[j]*s1[j]);
                    ss[j]=ns; cc[j]=nc;
                }
            }
            asm volatile("cp.async.wait_group 0;");
            __syncthreads();
            if (hn){
#pragma unroll
                for (int mq=0; mq<2; ++mq){
                    int mtile = wid*2+mq, b = mq*8;
                    Af[nxt][mtile*2+0][lane] = make_uint4(ph2(ss[b+0],ss[b+1]), ph2(ss[b+4],ss[b+5]),
                                                          ph2(ss[b+2],ss[b+3]), ph2(ss[b+6],ss[b+7]));
                    Af[nxt][mtile*2+1][lane] = make_uint4(ph2(cc[b+0],cc[b+1]), ph2(cc[b+4],cc[b+5]),
                                                          ph2(cc[b+2],cc[b+3]), ph2(cc[b+6],cc[b+7]));
                }
                size_t go = (size_t)(g+1)*GST;
                cpa16(cdst[0] + nxt*5120u, gb0 + go);
                cpa16(cdst[1] + nxt*5120u, gb1 + go);
                asm volatile("cp.async.commit_group;");
            }
            // ---- GEMM: 128m x 64n x 32k (fp16 HMMA), warp = 64m x 32n ----
#pragma unroll
            for (int kt=0; kt<2; ++kt){
                uint4 av[4];
#pragma unroll
                for (int mt=0;mt<4;++mt) av[mt] = Af[cur][(wm*4+mt)*2 + kt][lane];
#pragma unroll
                for (int nt=0;nt<4;++nt){
                    const __half* bp = &Bs[cur][wn*32 + nt*8 + gid][kt*16 + 2*tig];
                    uint32_t b0 = *(const uint32_t*)bp;
                    uint32_t b1 = *(const uint32_t*)(bp + 8);
#pragma unroll
                    for (int mt=0;mt<4;++mt) mma16(acc[mt][nt], av[mt], b0, b1);
                }
            }
            __syncthreads();
        }
    }

    // final flush
    if (cur_tile >= 0){
#pragma unroll
        for (int mt=0;mt<4;++mt)
#pragma unroll
        for (int nt=0;nt<4;++nt){
            float* op = out + (size_t)(cm0 + wm*64 + mt*16 + gid)*512 + cn0 + wn*32 + nt*8 + 2*tig;
            atomicAdd(op,      acc[mt][nt][0]*SC);
            atomicAdd(op+1,    acc[mt][nt][1]*SC);
            atomicAdd(op+4096, acc[mt][nt][2]*SC);
            atomicAdd(op+4097, acc[mt][nt][3]*SC);
        }
    }
}

extern "C" void kernel_launch(void* const* d_in, const int* in_sizes, int n_in,
                              void* d_out, int out_size) {
    const float* x    = (const float*)d_in[0];
    const float* fc   = (const float*)d_in[1];
    const float* bias = (const float*)d_in[2];
    float* out = (float*)d_out;

    init_out_kernel<<<1024, 256>>>(bias, out);
    prep_kernel<<<dim3(16,16,100), dim3(32,8)>>>(fc);
    fkan_fp16<<<NCTAS, 128>>>(x, out);
}